// round 1
// baseline (speedup 1.0000x reference)
#include <cuda_runtime.h>
#include <cuda_bf16.h>

// Problem constants (fixed by the reference setup)
#define NMAX  500000
#define KINST 512
#define DFEAT 256
#define HID   64
#define OUTC  32
#define NSEG  (KINST + 1)   // +1 dummy segment for background (-1)

// Device-global scratch (no allocations allowed)
__device__ int   g_counts[NSEG];
__device__ int   g_offsets[NSEG];
__device__ int   g_cursor[NSEG];
__device__ float g_csum[KINST * 3];
__device__ int   g_sorted[NMAX];

// ---------------------------------------------------------------------------
// 1) zero scratch
__global__ void k_zero() {
    int t = blockIdx.x * blockDim.x + threadIdx.x;
    if (t < NSEG) { g_counts[t] = 0; g_cursor[t] = 0; }
    if (t < KINST * 3) g_csum[t] = 0.0f;
}

// ---------------------------------------------------------------------------
// 2) histogram of segment ids + coordinate sums (cheap atomics: few addresses)
__global__ void k_hist(const int* __restrict__ ids,
                       const float* __restrict__ coords, int n) {
    int i = blockIdx.x * blockDim.x + threadIdx.x;
    if (i >= n) return;
    int id  = ids[i];
    int seg = (id >= 0) ? id : KINST;
    atomicAdd(&g_counts[seg], 1);
    if (id >= 0) {
        atomicAdd(&g_csum[id * 3 + 0], coords[i * 3 + 0]);
        atomicAdd(&g_csum[id * 3 + 1], coords[i * 3 + 1]);
        atomicAdd(&g_csum[id * 3 + 2], coords[i * 3 + 2]);
    }
}

// ---------------------------------------------------------------------------
// 3) exclusive prefix sum over 513 counts (single block, Hillis-Steele)
__global__ void k_scan() {
    __shared__ int a[1024];
    int t = threadIdx.x;
    int v = (t < NSEG) ? g_counts[t] : 0;
    a[t] = v;
    __syncthreads();
    for (int s = 1; s < 1024; s <<= 1) {
        int x = (t >= s) ? a[t - s] : 0;
        __syncthreads();
        a[t] += x;
        __syncthreads();
    }
    if (t < NSEG) g_offsets[t] = a[t] - v;   // exclusive
}

// ---------------------------------------------------------------------------
// 4) bucket point indices by segment
__global__ void k_scatter(const int* __restrict__ ids, int n) {
    int i = blockIdx.x * blockDim.x + threadIdx.x;
    if (i >= n) return;
    int id  = ids[i];
    int seg = (id >= 0) ? id : KINST;
    int pos = g_offsets[seg] + atomicAdd(&g_cursor[seg], 1);
    g_sorted[pos] = i;
}

// ---------------------------------------------------------------------------
// 5) segment mean of features (the 512 MB kernel) + centroids.
//    One block per instance; thread t owns feature column t.
//    Indices staged through smem in batches of 256; inner loop unrolled so
//    8 independent LDGs per thread are in flight (hides DRAM latency).
__global__ void __launch_bounds__(DFEAT, 4)
k_reduce(const float* __restrict__ feat, float* __restrict__ out) {
    int k = blockIdx.x;
    int t = threadIdx.x;                // 0..255
    int base = g_offsets[k];
    int c    = g_counts[k];
    float inv = 1.0f / (float)((c > 1) ? c : 1);

    __shared__ int sidx[256];
    float s = 0.0f;
    for (int j0 = 0; j0 < c; j0 += 256) {
        int m = min(256, c - j0);
        __syncthreads();
        if (t < m) sidx[t] = g_sorted[base + j0 + t];
        __syncthreads();
        #pragma unroll 8
        for (int j = 0; j < m; j++) {
            s += feat[(size_t)sidx[j] * DFEAT + t];
        }
    }
    out[(size_t)k * DFEAT + t] = s * inv;
    if (t < 3) out[KINST * DFEAT + k * 3 + t] = g_csum[k * 3 + t] * inv;
}

// ---------------------------------------------------------------------------
// 6) tiny MLP on the 512 embeddings:
//    relu(emb @ W1) -> relu(@ W2) -> @ W3 + b3
__global__ void __launch_bounds__(HID)
k_mlp(const float* __restrict__ outbuf,
      const float* __restrict__ W1, const float* __restrict__ W2,
      const float* __restrict__ W3, const float* __restrict__ b3,
      float* __restrict__ out) {
    int k = blockIdx.x;
    int t = threadIdx.x;                // 0..63
    __shared__ float emb[DFEAT];
    __shared__ float h1[HID];
    __shared__ float h2[HID];

    const float* e = outbuf + (size_t)k * DFEAT;   // embeddings written by k_reduce
    for (int i = t; i < DFEAT; i += HID) emb[i] = e[i];
    __syncthreads();

    float s = 0.0f;
    #pragma unroll 4
    for (int i = 0; i < DFEAT; i++) s += emb[i] * W1[i * HID + t];
    h1[t] = fmaxf(s, 0.0f);
    __syncthreads();

    s = 0.0f;
    #pragma unroll 4
    for (int i = 0; i < HID; i++) s += h1[i] * W2[i * HID + t];
    h2[t] = fmaxf(s, 0.0f);
    __syncthreads();

    if (t < OUTC) {
        s = b3[t];
        #pragma unroll 4
        for (int i = 0; i < HID; i++) s += h2[i] * W3[i * OUTC + t];
        out[KINST * DFEAT + KINST * 3 + k * OUTC + t] = s;
    }
}

// ---------------------------------------------------------------------------
extern "C" void kernel_launch(void* const* d_in, const int* in_sizes, int n_in,
                              void* d_out, int out_size) {
    const float* feat   = (const float*)d_in[0];
    const float* coords = (const float*)d_in[1];
    const int*   ids    = (const int*)d_in[2];

    // num_instances may appear as a 1-element scalar input between ids and W1
    int wi = 3;
    if (n_in > 3 && in_sizes[3] == 1) wi = 4;
    const float* W1 = (const float*)d_in[wi];
    const float* W2 = (const float*)d_in[wi + 1];
    const float* W3 = (const float*)d_in[wi + 2];
    const float* b3 = (const float*)d_in[wi + 3];

    int n = in_sizes[2];                 // number of points
    float* out = (float*)d_out;

    int nb = (n + 255) / 256;
    k_zero<<<(KINST * 3 + 255) / 256, 256>>>();
    k_hist<<<nb, 256>>>(ids, coords, n);
    k_scan<<<1, 1024>>>();
    k_scatter<<<nb, 256>>>(ids, n);
    k_reduce<<<KINST, DFEAT>>>(feat, out);
    k_mlp<<<KINST, HID>>>(out, W1, W2, W3, b3, out);
}

// round 2
// speedup vs baseline: 2.0912x; 2.0912x over previous
#include <cuda_runtime.h>
#include <cuda_bf16.h>

// Problem constants (fixed by the reference setup)
#define NMAX  500000
#define KINST 512
#define DFEAT 256
#define HID   64
#define OUTC  32
#define NSEG  (KINST + 1)   // +1 dummy segment for background (-1)
#define PAD   32            // one counter per 128B line

// Device-global scratch (no allocations allowed).
// All contended atomic targets are padded: one per 128-byte L2 line.
__device__ int   g_counts[NSEG * PAD];   // padded histogram (atomic target)
__device__ int   g_offsets[NSEG];        // exclusive scan (read-only after k_scan)
__device__ float g_csum[KINST * PAD];    // padded: row k holds 3 floats at k*PAD
__device__ int   g_rank[NMAX];           // per-point rank within its segment
__device__ int   g_sorted[NMAX];         // point indices bucketed by segment

// ---------------------------------------------------------------------------
// 1) zero padded scratch
__global__ void k_zero() {
    int t = blockIdx.x * blockDim.x + threadIdx.x;
    if (t < NSEG * PAD)  g_counts[t] = 0;
    if (t < KINST * PAD) g_csum[t] = 0.0f;
}

// ---------------------------------------------------------------------------
// 2) histogram + rank assignment + coordinate sums.
//    All atomic targets padded to distinct 128B lines -> spread across L2 slices.
__global__ void k_hist(const int* __restrict__ ids,
                       const float* __restrict__ coords, int n) {
    int i = blockIdx.x * blockDim.x + threadIdx.x;
    if (i >= n) return;
    int id  = ids[i];
    int seg = (id >= 0) ? id : KINST;
    g_rank[i] = atomicAdd(&g_counts[seg * PAD], 1);
    if (id >= 0) {
        atomicAdd(&g_csum[id * PAD + 0], coords[i * 3 + 0]);
        atomicAdd(&g_csum[id * PAD + 1], coords[i * 3 + 1]);
        atomicAdd(&g_csum[id * PAD + 2], coords[i * 3 + 2]);
    }
}

// ---------------------------------------------------------------------------
// 3) exclusive prefix sum over 513 counts (single block, Hillis-Steele)
__global__ void k_scan() {
    __shared__ int a[1024];
    int t = threadIdx.x;
    int v = (t < NSEG) ? g_counts[t * PAD] : 0;
    a[t] = v;
    __syncthreads();
    for (int s = 1; s < 1024; s <<= 1) {
        int x = (t >= s) ? a[t - s] : 0;
        __syncthreads();
        a[t] += x;
        __syncthreads();
    }
    if (t < NSEG) g_offsets[t] = a[t] - v;   // exclusive
}

// ---------------------------------------------------------------------------
// 4) bucket point indices by segment — atomic-free (rank precomputed)
__global__ void k_scatter(const int* __restrict__ ids, int n) {
    int i = blockIdx.x * blockDim.x + threadIdx.x;
    if (i >= n) return;
    int id  = ids[i];
    int seg = (id >= 0) ? id : KINST;
    g_sorted[g_offsets[seg] + g_rank[i]] = i;
}

// ---------------------------------------------------------------------------
// 5) segment mean of features (the 512 MB kernel) + centroids.
//    One block (256 thr) per instance. Thread layout: group g = t>>6 owns every
//    4th point; feature-quad f = t&63 owns features [4f, 4f+4). Each thread
//    accumulates a float4 via LDG.128 (warp covers a full contiguous 1KB row
//    half -> perfectly coalesced). Final 4-way cross-group smem reduction.
__global__ void __launch_bounds__(256, 4)
k_reduce(const float* __restrict__ feat, float* __restrict__ out) {
    int k = blockIdx.x;
    int t = threadIdx.x;                // 0..255
    int g = t >> 6;                     // 0..3  point-interleave group
    int f = t & 63;                     // 0..63 feature quad
    int base = g_offsets[k];
    int c    = g_counts[k * PAD];
    float inv = 1.0f / (float)((c > 1) ? c : 1);

    __shared__ int    sidx[512];
    __shared__ float4 red[256];

    float4 acc = make_float4(0.f, 0.f, 0.f, 0.f);
    for (int j0 = 0; j0 < c; j0 += 512) {
        int m = min(512, c - j0);
        __syncthreads();
        if (t < m)        sidx[t]       = g_sorted[base + j0 + t];
        if (t + 256 < m)  sidx[t + 256] = g_sorted[base + j0 + t + 256];
        __syncthreads();
        #pragma unroll 4
        for (int j = g; j < m; j += 4) {
            const float4* row = (const float4*)(feat + (size_t)sidx[j] * DFEAT);
            float4 v = __ldg(&row[f]);
            acc.x += v.x; acc.y += v.y; acc.z += v.z; acc.w += v.w;
        }
    }
    red[t] = acc;
    __syncthreads();
    if (t < 64) {
        float4 a0 = red[t], a1 = red[t + 64], a2 = red[t + 128], a3 = red[t + 192];
        float4 r;
        r.x = (a0.x + a1.x + a2.x + a3.x) * inv;
        r.y = (a0.y + a1.y + a2.y + a3.y) * inv;
        r.z = (a0.z + a1.z + a2.z + a3.z) * inv;
        r.w = (a0.w + a1.w + a2.w + a3.w) * inv;
        ((float4*)(out + (size_t)k * DFEAT))[t] = r;
    }
    if (t < 3) out[KINST * DFEAT + k * 3 + t] = g_csum[k * PAD + t] * inv;
}

// ---------------------------------------------------------------------------
// 6) tiny MLP on the 512 embeddings:
//    relu(emb @ W1) -> relu(@ W2) -> @ W3 + b3
__global__ void __launch_bounds__(HID)
k_mlp(const float* __restrict__ outbuf,
      const float* __restrict__ W1, const float* __restrict__ W2,
      const float* __restrict__ W3, const float* __restrict__ b3,
      float* __restrict__ out) {
    int k = blockIdx.x;
    int t = threadIdx.x;                // 0..63
    __shared__ float emb[DFEAT];
    __shared__ float h1[HID];
    __shared__ float h2[HID];

    const float* e = outbuf + (size_t)k * DFEAT;   // embeddings written by k_reduce
    for (int i = t; i < DFEAT; i += HID) emb[i] = e[i];
    __syncthreads();

    float s = 0.0f;
    #pragma unroll 4
    for (int i = 0; i < DFEAT; i++) s += emb[i] * W1[i * HID + t];
    h1[t] = fmaxf(s, 0.0f);
    __syncthreads();

    s = 0.0f;
    #pragma unroll 4
    for (int i = 0; i < HID; i++) s += h1[i] * W2[i * HID + t];
    h2[t] = fmaxf(s, 0.0f);
    __syncthreads();

    if (t < OUTC) {
        s = b3[t];
        #pragma unroll 4
        for (int i = 0; i < HID; i++) s += h2[i] * W3[i * OUTC + t];
        out[KINST * DFEAT + KINST * 3 + k * OUTC + t] = s;
    }
}

// ---------------------------------------------------------------------------
extern "C" void kernel_launch(void* const* d_in, const int* in_sizes, int n_in,
                              void* d_out, int out_size) {
    const float* feat   = (const float*)d_in[0];
    const float* coords = (const float*)d_in[1];
    const int*   ids    = (const int*)d_in[2];

    // num_instances may appear as a 1-element scalar input between ids and W1
    int wi = 3;
    if (n_in > 3 && in_sizes[3] == 1) wi = 4;
    const float* W1 = (const float*)d_in[wi];
    const float* W2 = (const float*)d_in[wi + 1];
    const float* W3 = (const float*)d_in[wi + 2];
    const float* b3 = (const float*)d_in[wi + 3];

    int n = in_sizes[2];                 // number of points
    float* out = (float*)d_out;

    int nb = (n + 255) / 256;
    k_zero<<<(NSEG * PAD + 255) / 256, 256>>>();
    k_hist<<<nb, 256>>>(ids, coords, n);
    k_scan<<<1, 1024>>>();
    k_scatter<<<nb, 256>>>(ids, n);
    k_reduce<<<KINST, 256>>>(feat, out);
    k_mlp<<<KINST, HID>>>(out, W1, W2, W3, b3, out);
}

// round 3
// speedup vs baseline: 2.4023x; 1.1488x over previous
#include <cuda_runtime.h>
#include <cuda_bf16.h>

// Problem constants (fixed by the reference setup)
#define NMAX  500000
#define KINST 512
#define DFEAT 256
#define HID   64
#define OUTC  32
#define NSEG  (KINST + 1)   // +1 dummy segment for background (-1)
#define PAD   32            // one counter per 128B line
#define SPLIT 4             // blocks per instance in the reduce phase

// Device-global scratch (no allocations allowed).
__device__ int    g_counts[NSEG * PAD];     // padded histogram (atomic target)
__device__ int    g_offsets[NSEG];          // exclusive scan
__device__ float  g_csum[KINST * PAD];      // padded: row k holds 3 floats at k*PAD
__device__ int    g_rank[NMAX];             // per-point rank within its segment
__device__ int    g_sorted[NMAX];           // point indices bucketed by segment
__device__ float4 g_partial[KINST * SPLIT * 64];  // per-split partial feature sums

// ---------------------------------------------------------------------------
// 1) zero padded scratch
__global__ void k_zero() {
    int t = blockIdx.x * blockDim.x + threadIdx.x;
    if (t < NSEG * PAD)  g_counts[t] = 0;
    if (t < KINST * PAD) g_csum[t] = 0.0f;
}

// ---------------------------------------------------------------------------
// 2) histogram + rank assignment + coordinate sums (padded atomic targets)
__global__ void k_hist(const int* __restrict__ ids,
                       const float* __restrict__ coords, int n) {
    int i = blockIdx.x * blockDim.x + threadIdx.x;
    if (i >= n) return;
    int id  = ids[i];
    int seg = (id >= 0) ? id : KINST;
    g_rank[i] = atomicAdd(&g_counts[seg * PAD], 1);
    if (id >= 0) {
        atomicAdd(&g_csum[id * PAD + 0], coords[i * 3 + 0]);
        atomicAdd(&g_csum[id * PAD + 1], coords[i * 3 + 1]);
        atomicAdd(&g_csum[id * PAD + 2], coords[i * 3 + 2]);
    }
}

// ---------------------------------------------------------------------------
// 3) exclusive prefix sum over 513 counts (single block, Hillis-Steele)
__global__ void k_scan() {
    __shared__ int a[1024];
    int t = threadIdx.x;
    int v = (t < NSEG) ? g_counts[t * PAD] : 0;
    a[t] = v;
    __syncthreads();
    for (int s = 1; s < 1024; s <<= 1) {
        int x = (t >= s) ? a[t - s] : 0;
        __syncthreads();
        a[t] += x;
        __syncthreads();
    }
    if (t < NSEG) g_offsets[t] = a[t] - v;   // exclusive
}

// ---------------------------------------------------------------------------
// 4) bucket point indices by segment — atomic-free (rank precomputed)
__global__ void k_scatter(const int* __restrict__ ids, int n) {
    int i = blockIdx.x * blockDim.x + threadIdx.x;
    if (i >= n) return;
    int id  = ids[i];
    int seg = (id >= 0) ? id : KINST;
    g_sorted[g_offsets[seg] + g_rank[i]] = i;
}

// ---------------------------------------------------------------------------
// 5) partial segment sums of features (the 512 MB kernel).
//    SPLIT blocks per instance, each owning a contiguous chunk of the
//    instance's sorted points -> fine-grained load balance (2048 blocks).
//    Thread layout: group g = t>>6 interleaves points, quad f = t&63 owns
//    features [4f,4f+4). LDG.128 streaming loads (__ldcs: read-once data).
__global__ void __launch_bounds__(256, 4)
k_partial(const float* __restrict__ feat) {
    int bid = blockIdx.x;
    int k = bid >> 2;                   // instance
    int s = bid & (SPLIT - 1);          // chunk within instance
    int t = threadIdx.x;                // 0..255
    int g = t >> 6;                     // 0..3  point-interleave group
    int f = t & 63;                     // 0..63 feature quad
    int base = g_offsets[k];
    int c    = g_counts[k * PAD];
    int jlo = (c * s) >> 2;
    int jhi = (c * (s + 1)) >> 2;

    __shared__ int    sidx[256];
    __shared__ float4 red[256];

    float4 acc = make_float4(0.f, 0.f, 0.f, 0.f);
    for (int j0 = jlo; j0 < jhi; j0 += 256) {
        int m = min(256, jhi - j0);
        __syncthreads();
        if (t < m) sidx[t] = g_sorted[base + j0 + t];
        __syncthreads();
        #pragma unroll 8
        for (int j = g; j < m; j += 4) {
            const float4* row = (const float4*)(feat + (size_t)sidx[j] * DFEAT);
            float4 v = __ldcs(&row[f]);
            acc.x += v.x; acc.y += v.y; acc.z += v.z; acc.w += v.w;
        }
    }
    red[t] = acc;
    __syncthreads();
    if (t < 64) {
        float4 a0 = red[t], a1 = red[t + 64], a2 = red[t + 128], a3 = red[t + 192];
        float4 r;
        r.x = a0.x + a1.x + a2.x + a3.x;
        r.y = a0.y + a1.y + a2.y + a3.y;
        r.z = a0.z + a1.z + a2.z + a3.z;
        r.w = a0.w + a1.w + a2.w + a3.w;
        g_partial[bid * 64 + t] = r;
    }
}

// ---------------------------------------------------------------------------
// 6) finalize (combine SPLIT partials, divide) + centroids + tiny MLP
__global__ void __launch_bounds__(HID)
k_mlp(const float* __restrict__ W1, const float* __restrict__ W2,
      const float* __restrict__ W3, const float* __restrict__ b3,
      float* __restrict__ out) {
    int k = blockIdx.x;
    int t = threadIdx.x;                // 0..63
    __shared__ float emb[DFEAT];
    __shared__ float h1[HID];
    __shared__ float h2[HID];

    int c = g_counts[k * PAD];
    float inv = 1.0f / (float)((c > 1) ? c : 1);

    // deterministic 4-way combine of partial sums, then mean
    float4 p0 = g_partial[(k * SPLIT + 0) * 64 + t];
    float4 p1 = g_partial[(k * SPLIT + 1) * 64 + t];
    float4 p2 = g_partial[(k * SPLIT + 2) * 64 + t];
    float4 p3 = g_partial[(k * SPLIT + 3) * 64 + t];
    float4 r;
    r.x = (p0.x + p1.x + p2.x + p3.x) * inv;
    r.y = (p0.y + p1.y + p2.y + p3.y) * inv;
    r.z = (p0.z + p1.z + p2.z + p3.z) * inv;
    r.w = (p0.w + p1.w + p2.w + p3.w) * inv;
    ((float4*)(out + (size_t)k * DFEAT))[t] = r;     // embeddings
    ((float4*)emb)[t] = r;
    if (t < 3) out[KINST * DFEAT + k * 3 + t] = g_csum[k * PAD + t] * inv;  // centroids
    __syncthreads();

    float s = 0.0f;
    #pragma unroll 4
    for (int i = 0; i < DFEAT; i++) s += emb[i] * W1[i * HID + t];
    h1[t] = fmaxf(s, 0.0f);
    __syncthreads();

    s = 0.0f;
    #pragma unroll 4
    for (int i = 0; i < HID; i++) s += h1[i] * W2[i * HID + t];
    h2[t] = fmaxf(s, 0.0f);
    __syncthreads();

    if (t < OUTC) {
        s = b3[t];
        #pragma unroll 4
        for (int i = 0; i < HID; i++) s += h2[i] * W3[i * OUTC + t];
        out[KINST * DFEAT + KINST * 3 + k * OUTC + t] = s;
    }
}

// ---------------------------------------------------------------------------
extern "C" void kernel_launch(void* const* d_in, const int* in_sizes, int n_in,
                              void* d_out, int out_size) {
    const float* feat   = (const float*)d_in[0];
    const float* coords = (const float*)d_in[1];
    const int*   ids    = (const int*)d_in[2];

    // num_instances may appear as a 1-element scalar input between ids and W1
    int wi = 3;
    if (n_in > 3 && in_sizes[3] == 1) wi = 4;
    const float* W1 = (const float*)d_in[wi];
    const float* W2 = (const float*)d_in[wi + 1];
    const float* W3 = (const float*)d_in[wi + 2];
    const float* b3 = (const float*)d_in[wi + 3];

    int n = in_sizes[2];                 // number of points
    float* out = (float*)d_out;

    int nb = (n + 255) / 256;
    k_zero<<<(NSEG * PAD + 255) / 256, 256>>>();
    k_hist<<<nb, 256>>>(ids, coords, n);
    k_scan<<<1, 1024>>>();
    k_scatter<<<nb, 256>>>(ids, n);
    k_partial<<<KINST * SPLIT, 256>>>(feat);
    k_mlp<<<KINST, HID>>>(W1, W2, W3, b3, out);
}